// round 2
// baseline (speedup 1.0000x reference)
#include <cuda_runtime.h>
#include <cstddef>

typedef unsigned long long ull;

#define L_DIM  4096
#define D_DIM  150
#define DP     160          // padded N (compute 160, store 150)
#define BM     128          // CTA M tile
#define BK     16           // K tile
#define SPLITK 16
#define KCHUNK (L_DIM / SPLITK)   // 256
#define APAD2  (2 * BM + 4)       // duplicated A row (floats), 16B-aligned rows

// Split-K partials: SPLITK * L * DP floats = 41.9 MB static device scratch.
__device__ float g_scratch[(size_t)SPLITK * L_DIM * DP];

// Packed dual-FMA: c.{lo,hi} += a.{lo,hi} * b.{lo,hi}  (Blackwell f32x2 pipe)
#define FMA2(c, a, b) \
    asm("fma.rn.f32x2 %0, %1, %2, %0;" : "+l"(c) : "l"(a), "l"(b))

// out[m,d] = sum_k Aeff[m,k] * h[k,d]
//   TRANS=false : Aeff[m,k] = adj[m,k,0]+adj[m,k,1]   -> h_out = A @ h
//   TRANS=true  : Aeff[m,k] = adj[k,m,0]+adj[k,m,1]   -> h_in  = A^T @ h
template <bool TRANS>
__global__ __launch_bounds__(256, 2)
void gemm_kernel(const float* __restrict__ adj, const float* __restrict__ h)
{
    // A stored duplicated: a_s2[k][2*m] == a_s2[k][2*m+1] == A[m,k]
    __shared__ __align__(16) float a_s2[BK][APAD2];
    __shared__ __align__(16) float b_s[BK][DP];

    const int tid   = threadIdx.x;
    const int tx    = tid & 15;        // N-dim thread coord (0..15) -> 10 d's
    const int ty    = tid >> 4;        // M-dim thread coord (0..15) -> 8 m's
    const int mBase = blockIdx.x * BM;
    const int kBase = blockIdx.y * KCHUNK;

    ull acc[8][5];                     // 8 m x 5 d-pairs, packed f32x2
    #pragma unroll
    for (int u = 0; u < 8; u++)
        #pragma unroll
        for (int v = 0; v < 5; v++)
            acc[u][v] = 0ull;

    for (int kt = 0; kt < KCHUNK; kt += BK) {
        const int k0 = kBase + kt;

        // ---- load A tile (128 m x 16 k), sum 2 edge channels, store duplicated ----
        #pragma unroll
        for (int r = 0; r < 4; r++) {
            const int f = tid + 256 * r;
            if constexpr (!TRANS) {
                const int row = f >> 3;     // m offset 0..127
                const int seg = f & 7;      // k-pair index 0..7
                const float4 v = *reinterpret_cast<const float4*>(
                    adj + ((size_t)(mBase + row) * (2 * L_DIM) + (size_t)k0 * 2 + seg * 4));
                const float p = v.x + v.y;  // k = seg*2
                const float q = v.z + v.w;  // k = seg*2+1
                *reinterpret_cast<float2*>(&a_s2[seg * 2 + 0][2 * row]) = make_float2(p, p);
                *reinterpret_cast<float2*>(&a_s2[seg * 2 + 1][2 * row]) = make_float2(q, q);
            } else {
                const int koff = f >> 6;    // k offset 0..15
                const int seg  = f & 63;    // m-pair index 0..63
                const float4 v = *reinterpret_cast<const float4*>(
                    adj + ((size_t)(k0 + koff) * (2 * L_DIM) + (size_t)mBase * 2 + seg * 4));
                const float p = v.x + v.y;  // m = seg*2
                const float q = v.z + v.w;  // m = seg*2+1
                *reinterpret_cast<float4*>(&a_s2[koff][4 * seg]) = make_float4(p, p, q, q);
            }
        }

        // ---- load B tile: h[k0..k0+15][0..159] (zero-pad d>=150) ----
        #pragma unroll
        for (int r = 0; r < 10; r++) {
            const int g  = tid + 256 * r;      // 0..2559
            const int kk = g / DP;
            const int d  = g - kk * DP;
            float val = 0.0f;
            if (d < D_DIM)
                val = __ldg(h + (size_t)(k0 + kk) * D_DIM + d);
            b_s[kk][d] = val;
        }

        __syncthreads();

        // ---- compute: 16 k-steps x (8 m x 10 d) via packed f32x2 ----
        #pragma unroll
        for (int kk = 0; kk < BK; kk++) {
            // B operand: 5 packed d-pairs for this thread
            const ulonglong2 bb0 = *reinterpret_cast<const ulonglong2*>(&b_s[kk][tx * 4]);
            const ulonglong2 bb1 = *reinterpret_cast<const ulonglong2*>(&b_s[kk][64 + tx * 4]);
            const ull        bb2 = *reinterpret_cast<const ull*>(&b_s[kk][128 + tx * 2]);
            ull b[5];
            b[0] = bb0.x; b[1] = bb0.y; b[2] = bb1.x; b[3] = bb1.y; b[4] = bb2;

            const ull* arow = reinterpret_cast<const ull*>(&a_s2[kk][2 * (ty * 8)]);
            #pragma unroll
            for (int u = 0; u < 8; u++) {
                const ull a2 = arow[u];   // (a,a) duplicated pair, LDS.64 broadcast
                FMA2(acc[u][0], a2, b[0]);
                FMA2(acc[u][1], a2, b[1]);
                FMA2(acc[u][2], a2, b[2]);
                FMA2(acc[u][3], a2, b[3]);
                FMA2(acc[u][4], a2, b[4]);
            }
        }

        __syncthreads();
    }

    // ---- epilogue: packed accs are d-contiguous; store directly ----
    float* sp = g_scratch + (size_t)blockIdx.y * ((size_t)L_DIM * DP);
    #pragma unroll
    for (int u = 0; u < 8; u++) {
        const int row = mBase + ty * 8 + u;
        float* rp = sp + (size_t)row * DP;
        ulonglong2 s0; s0.x = acc[u][0]; s0.y = acc[u][1];
        ulonglong2 s1; s1.x = acc[u][2]; s1.y = acc[u][3];
        *reinterpret_cast<ulonglong2*>(rp + tx * 4)      = s0;
        *reinterpret_cast<ulonglong2*>(rp + 64 + tx * 4) = s1;
        *reinterpret_cast<ull*>(rp + 128 + tx * 2)       = acc[u][4];
    }
}

// Deterministic split-K reduction: out[row*D + d] = sum_s scratch[s][row][d]
__global__ void reduce_kernel(float* __restrict__ out)
{
    const int idx = blockIdx.x * 256 + threadIdx.x;
    if (idx >= L_DIM * D_DIM) return;
    const int row = idx / D_DIM;
    const int d   = idx - row * D_DIM;
    const size_t base = (size_t)row * DP + d;
    float s = 0.0f;
    #pragma unroll
    for (int sk = 0; sk < SPLITK; sk++)
        s += g_scratch[(size_t)sk * ((size_t)L_DIM * DP) + base];
    out[idx] = s;
}

extern "C" void kernel_launch(void* const* d_in, const int* in_sizes, int n_in,
                              void* d_out, int out_size)
{
    const float* adj = (const float*)d_in[0];   // [L, L, 2] fp32
    const float* h   = (const float*)d_in[1];   // [L, D]    fp32
    float* out = (float*)d_out;                 // [2, L, D] : h_in then h_out

    const dim3 gemm_grid(L_DIM / BM, SPLITK);
    const int  red_blocks = (L_DIM * D_DIM + 255) / 256;

    // h_out = A @ h  -> second half of output
    gemm_kernel<false><<<gemm_grid, 256>>>(adj, h);
    reduce_kernel<<<red_blocks, 256>>>(out + (size_t)L_DIM * D_DIM);

    // h_in = A^T @ h -> first half of output
    gemm_kernel<true><<<gemm_grid, 256>>>(adj, h);
    reduce_kernel<<<red_blocks, 256>>>(out);
}

// round 6
// speedup vs baseline: 1.9757x; 1.9757x over previous
#include <cuda_runtime.h>
#include <cuda_fp16.h>
#include <cstdint>
#include <cstddef>

#define L_DIM 4096
#define D_DIM 150
#define DP    160            // padded N
#define BM    64
#define BK    32             // 2 k16 steps per chunk
#define SPLITK 8
#define KCHUNK (L_DIM / SPLITK)   // 512
#define NCHUNK (KCHUNK / BK)      // 16
#define ASTRIDE 40           // halves per A smem row (pad: conflict-free, 16B-aligned)
#define BSTRIDE 40           // halves per B smem row

__device__ float  g_scratch[(size_t)SPLITK * L_DIM * DP];   // 21 MB
__device__ __half g_hT_hi[(size_t)DP * L_DIM];              // 1.3 MB, [n][k] K-major
__device__ __half g_hT_lo[(size_t)DP * L_DIM];

#define MMA16816(c0,c1,c2,c3, a0,a1,a2,a3, b0,b1)                            \
    asm volatile("mma.sync.aligned.m16n8k16.row.col.f32.f16.f16.f32 "        \
                 "{%0,%1,%2,%3}, {%4,%5,%6,%7}, {%8,%9}, {%0,%1,%2,%3};"     \
                 : "+f"(c0), "+f"(c1), "+f"(c2), "+f"(c3)                    \
                 : "r"(a0), "r"(a1), "r"(a2), "r"(a3), "r"(b0), "r"(b1))

__device__ __forceinline__ void f16_split(float v, __half& hi, __half& lo) {
    hi = __float2half_rn(v);
    lo = __float2half_rn(v - __half2float(hi));
}

// Precompute hT_hi/lo[n][k] = fp16 split of h[k][n] (zero-pad n >= 150)
__global__ void prep_h_kernel(const float* __restrict__ h) {
    const int idx = blockIdx.x * 256 + threadIdx.x;   // DP*L = 655360
    const int n = idx >> 12;
    const int k = idx & (L_DIM - 1);
    float v = 0.0f;
    if (n < D_DIM) v = h[(size_t)k * D_DIM + n];
    __half hi, lo;
    f16_split(v, hi, lo);
    g_hT_hi[idx] = hi;
    g_hT_lo[idx] = lo;
}

// partial[split][m][d] = sum_{k in split} Aeff[m,k] * h[k,d]  via 3xFP16 mma.sync
//   TRANS=false : Aeff[m,k] = adj[m,k,0]+adj[m,k,1]   (h_out)
//   TRANS=true  : Aeff[m,k] = adj[k,m,0]+adj[k,m,1]   (h_in)
template <bool TRANS>
__global__ __launch_bounds__(256)
void gemm_mma_kernel(const float* __restrict__ adj)
{
    __shared__ __align__(16) __half a_hi[BM * ASTRIDE];
    __shared__ __align__(16) __half a_lo[BM * ASTRIDE];
    __shared__ __align__(16) __half b_hi[DP * BSTRIDE];
    __shared__ __align__(16) __half b_lo[DP * BSTRIDE];

    const int tid  = threadIdx.x;
    const int wid  = tid >> 5;
    const int lane = tid & 31;
    const int wm   = wid & 1;         // warp M coord: 2 x 32 rows
    const int wn   = wid >> 1;        // warp N coord: 4 x 40 cols
    const int qid  = lane >> 2;       // 0..7
    const int qk   = lane & 3;        // 0..3

    const int mBase = blockIdx.x * BM;
    const int kBase = blockIdx.y * KCHUNK;

    float acc[2][5][4];
    #pragma unroll
    for (int i = 0; i < 2; i++)
        #pragma unroll
        for (int j = 0; j < 5; j++)
            #pragma unroll
            for (int t = 0; t < 4; t++)
                acc[i][j][t] = 0.0f;

    for (int it = 0; it < NCHUNK; it++) {
        const int k0 = kBase + it * BK;

        // ---- A tile: 64 m x 32 k from adj, channel-sum, fp16 split ----
        #pragma unroll
        for (int r = 0; r < 4; r++) {
            const int f = tid + 256 * r;           // 1024 float4
            if constexpr (!TRANS) {
                const int row = f >> 4;            // m 0..63
                const int s   = f & 15;            // k-pair (2s,2s+1)
                const float4 v = *reinterpret_cast<const float4*>(
                    adj + ((size_t)(mBase + row) * (2 * L_DIM) + (size_t)k0 * 2 + s * 4));
                __half ph, pl, qh, ql;
                f16_split(v.x + v.y, ph, pl);
                f16_split(v.z + v.w, qh, ql);
                const int o = row * ASTRIDE + 2 * s;
                *reinterpret_cast<__half2*>(&a_hi[o]) = __halves2half2(ph, qh);
                *reinterpret_cast<__half2*>(&a_lo[o]) = __halves2half2(pl, ql);
            } else {
                const int kk = f >> 5;             // k 0..31
                const int s  = f & 31;             // m-pair (2s,2s+1)
                const float4 v = *reinterpret_cast<const float4*>(
                    adj + ((size_t)(k0 + kk) * (2 * L_DIM) + (size_t)(mBase + 2 * s) * 2));
                __half ph, pl, qh, ql;
                f16_split(v.x + v.y, ph, pl);
                f16_split(v.z + v.w, qh, ql);
                a_hi[(2 * s) * ASTRIDE + kk]     = ph;
                a_lo[(2 * s) * ASTRIDE + kk]     = pl;
                a_hi[(2 * s + 1) * ASTRIDE + kk] = qh;
                a_lo[(2 * s + 1) * ASTRIDE + kk] = ql;
            }
        }

        // ---- B tile: 160 n x 32 k, hi+lo = 1280 uint4 loads (8 halves each) ----
        #pragma unroll
        for (int r = 0; r < 5; r++) {
            const int idx = tid + 256 * r;         // 0..1279
            const int half_sel = idx >= 640;       // 0: hi, 1: lo
            const int i2 = half_sel ? idx - 640 : idx;   // 0..639
            const int n = i2 >> 2;                 // 0..159
            const int s = i2 & 3;                  // 8-half group along k
            const __half* src = half_sel ? g_hT_lo : g_hT_hi;
            const uint4 v = *reinterpret_cast<const uint4*>(
                src + (size_t)n * L_DIM + k0 + s * 8);
            __half* dst = half_sel ? b_lo : b_hi;
            *reinterpret_cast<uint4*>(&dst[n * BSTRIDE + s * 8]) = v;
        }

        __syncthreads();

        // ---- compute: 2 k16 steps x (2 m-atoms x 5 n-atoms) x 3 split terms ----
        #pragma unroll
        for (int ks = 0; ks < 2; ks++) {
            const int kb = ks * 16;

            uint32_t ah[2][4], al[2][4];
            #pragma unroll
            for (int am = 0; am < 2; am++) {
                const int r0 = wm * 32 + am * 16 + qid;
                const int c0 = kb + qk * 2;
                ah[am][0] = *reinterpret_cast<const uint32_t*>(&a_hi[r0 * ASTRIDE + c0]);
                ah[am][1] = *reinterpret_cast<const uint32_t*>(&a_hi[(r0 + 8) * ASTRIDE + c0]);
                ah[am][2] = *reinterpret_cast<const uint32_t*>(&a_hi[r0 * ASTRIDE + c0 + 8]);
                ah[am][3] = *reinterpret_cast<const uint32_t*>(&a_hi[(r0 + 8) * ASTRIDE + c0 + 8]);
                al[am][0] = *reinterpret_cast<const uint32_t*>(&a_lo[r0 * ASTRIDE + c0]);
                al[am][1] = *reinterpret_cast<const uint32_t*>(&a_lo[(r0 + 8) * ASTRIDE + c0]);
                al[am][2] = *reinterpret_cast<const uint32_t*>(&a_lo[r0 * ASTRIDE + c0 + 8]);
                al[am][3] = *reinterpret_cast<const uint32_t*>(&a_lo[(r0 + 8) * ASTRIDE + c0 + 8]);
            }

            uint32_t bh[5][2], bl[5][2];
            #pragma unroll
            for (int an = 0; an < 5; an++) {
                const int n0 = wn * 40 + an * 8 + qid;
                const int c0 = kb + qk * 2;
                bh[an][0] = *reinterpret_cast<const uint32_t*>(&b_hi[n0 * BSTRIDE + c0]);
                bh[an][1] = *reinterpret_cast<const uint32_t*>(&b_hi[n0 * BSTRIDE + c0 + 8]);
                bl[an][0] = *reinterpret_cast<const uint32_t*>(&b_lo[n0 * BSTRIDE + c0]);
                bl[an][1] = *reinterpret_cast<const uint32_t*>(&b_lo[n0 * BSTRIDE + c0 + 8]);
            }

            #pragma unroll
            for (int am = 0; am < 2; am++)
                #pragma unroll
                for (int an = 0; an < 5; an++) {
                    float* c = acc[am][an];
                    MMA16816(c[0], c[1], c[2], c[3],
                             ah[am][0], ah[am][1], ah[am][2], ah[am][3],
                             bh[an][0], bh[an][1]);
                    MMA16816(c[0], c[1], c[2], c[3],
                             ah[am][0], ah[am][1], ah[am][2], ah[am][3],
                             bl[an][0], bl[an][1]);
                    MMA16816(c[0], c[1], c[2], c[3],
                             al[am][0], al[am][1], al[am][2], al[am][3],
                             bh[an][0], bh[an][1]);
                }
        }

        __syncthreads();
    }

    // ---- epilogue: write partials to this split's scratch slab ----
    float* sp = g_scratch + (size_t)blockIdx.y * ((size_t)L_DIM * DP);
    #pragma unroll
    for (int am = 0; am < 2; am++) {
        const int row = mBase + wm * 32 + am * 16 + qid;
        #pragma unroll
        for (int an = 0; an < 5; an++) {
            const int col = wn * 40 + an * 8 + qk * 2;
            *reinterpret_cast<float2*>(sp + (size_t)row * DP + col) =
                make_float2(acc[am][an][0], acc[am][an][1]);
            *reinterpret_cast<float2*>(sp + (size_t)(row + 8) * DP + col) =
                make_float2(acc[am][an][2], acc[am][an][3]);
        }
    }
}

// Deterministic split-K reduction
__global__ void reduce_kernel(float* __restrict__ out)
{
    const int idx = blockIdx.x * 256 + threadIdx.x;
    if (idx >= L_DIM * D_DIM) return;
    const int row = idx / D_DIM;
    const int d   = idx - row * D_DIM;
    const size_t base = (size_t)row * DP + d;
    float s = 0.0f;
    #pragma unroll
    for (int sk = 0; sk < SPLITK; sk++)
        s += g_scratch[(size_t)sk * ((size_t)L_DIM * DP) + base];
    out[idx] = s;
}

extern "C" void kernel_launch(void* const* d_in, const int* in_sizes, int n_in,
                              void* d_out, int out_size)
{
    const float* adj = (const float*)d_in[0];   // [L, L, 2] fp32
    const float* h   = (const float*)d_in[1];   // [L, D]    fp32
    float* out = (float*)d_out;                 // [2, L, D] : h_in then h_out

    prep_h_kernel<<<(DP * L_DIM) / 256, 256>>>(h);

    const dim3 grid(L_DIM / BM, SPLITK);
    const int  red_blocks = (L_DIM * D_DIM + 255) / 256;

    // h_out = A @ h  -> second half of output
    gemm_mma_kernel<false><<<grid, 256>>>(adj);
    reduce_kernel<<<red_blocks, 256>>>(out + (size_t)L_DIM * D_DIM);

    // h_in = A^T @ h -> first half of output
    gemm_mma_kernel<true><<<grid, 256>>>(adj);
    reduce_kernel<<<red_blocks, 256>>>(out);
}

// round 7
// speedup vs baseline: 2.8879x; 1.4617x over previous
#include <cuda_runtime.h>
#include <cuda_fp16.h>
#include <cstdint>
#include <cstddef>

#define L_DIM 4096
#define D_DIM 150
#define DP    160            // padded N
#define BM    64
#define BK    32             // 2 k16 steps per chunk
#define SPLITK 8
#define KCHUNK (L_DIM / SPLITK)   // 512
#define NCHUNK (KCHUNK / BK)      // 16
#define ASTRIDE 40           // halves per A smem row (80B: LDSM conflict-free)
#define BSTRIDE 40

#define ATILE (BM * ASTRIDE * 2)   // 5120 B
#define BTILE (DP * BSTRIDE * 2)   // 12800 B
// smem: a_hi[2] a_lo[2] b_hi[2] b_lo[2]
#define OFF_AHI(b) ((b) * ATILE)
#define OFF_ALO(b) (2 * ATILE + (b) * ATILE)
#define OFF_BHI(b) (4 * ATILE + (b) * BTILE)
#define OFF_BLO(b) (4 * ATILE + 2 * BTILE + (b) * BTILE)
#define SMEM_TOTAL (4 * ATILE + 4 * BTILE)   // 71680 B

__device__ float  g_scratch[(size_t)SPLITK * L_DIM * DP];   // 21 MB
__device__ __half g_hT_hi[(size_t)DP * L_DIM];              // [n][k] K-major
__device__ __half g_hT_lo[(size_t)DP * L_DIM];

#define MMA16816(c0,c1,c2,c3, a0,a1,a2,a3, b0,b1)                            \
    asm volatile("mma.sync.aligned.m16n8k16.row.col.f32.f16.f16.f32 "        \
                 "{%0,%1,%2,%3}, {%4,%5,%6,%7}, {%8,%9}, {%0,%1,%2,%3};"     \
                 : "+f"(c0), "+f"(c1), "+f"(c2), "+f"(c3)                    \
                 : "r"(a0), "r"(a1), "r"(a2), "r"(a3), "r"(b0), "r"(b1))

#define LDSM_X4(r0,r1,r2,r3, addr)                                           \
    asm volatile("ldmatrix.sync.aligned.m8n8.x4.shared.b16 {%0,%1,%2,%3}, [%4];" \
                 : "=r"(r0), "=r"(r1), "=r"(r2), "=r"(r3) : "r"(addr))

#define LDSM_X2(r0,r1, addr)                                                 \
    asm volatile("ldmatrix.sync.aligned.m8n8.x2.shared.b16 {%0,%1}, [%2];"   \
                 : "=r"(r0), "=r"(r1) : "r"(addr))

#define CPASYNC16(dst, src)                                                  \
    asm volatile("cp.async.cg.shared.global [%0], [%1], 16;" :: "r"(dst), "l"(src))
#define CPCOMMIT() asm volatile("cp.async.commit_group;")
#define CPWAIT0()  asm volatile("cp.async.wait_group 0;")

__device__ __forceinline__ void f16_split(float v, __half& hi, __half& lo) {
    hi = __float2half_rn(v);
    lo = __float2half_rn(v - __half2float(hi));
}

__global__ void prep_h_kernel(const float* __restrict__ h) {
    const int idx = blockIdx.x * 256 + threadIdx.x;   // DP*L
    const int n = idx >> 12;
    const int k = idx & (L_DIM - 1);
    float v = 0.0f;
    if (n < D_DIM) v = h[(size_t)k * D_DIM + n];
    __half hi, lo;
    f16_split(v, hi, lo);
    g_hT_hi[idx] = hi;
    g_hT_lo[idx] = lo;
}

template <bool TRANS>
__global__ __launch_bounds__(256)
void gemm_mma_kernel(const float* __restrict__ adj)
{
    extern __shared__ __align__(16) char smem[];
    uint32_t sbase;
    asm("{ .reg .u64 t; cvta.to.shared.u64 t, %1; cvt.u32.u64 %0, t; }"
        : "=r"(sbase) : "l"(smem));

    const int tid  = threadIdx.x;
    const int wid  = tid >> 5;
    const int lane = tid & 31;
    const int wm   = wid & 1;         // 2 x 32 rows
    const int wn   = wid >> 1;        // 4 x 40 cols
    const int qid  = lane >> 2;
    const int qk   = lane & 3;

    const int mBase = blockIdx.x * BM;
    const int kBase = blockIdx.y * KCHUNK;

    // per-thread ldmatrix address components (element units)
    const int a_row = ((lane >> 3) & 1) * 8 + (lane & 7);   // row within 16-atom
    const int a_col = (lane >> 4) * 8;                      // k-half select
    const int b_row = lane & 7;
    const int b_col = ((lane >> 3) & 1) * 8;

    float acc[2][5][4];
    #pragma unroll
    for (int i = 0; i < 2; i++)
        #pragma unroll
        for (int j = 0; j < 5; j++)
            #pragma unroll
            for (int t = 0; t < 4; t++)
                acc[i][j][t] = 0.0f;

    float rv[16];

    // ---- A global load (next tile) into registers ----
    auto loadA = [&](int it) {
        const int k0 = kBase + it * BK;
        if constexpr (!TRANS) {
            const int s = tid & 15;            // k-pair
            #pragma unroll
            for (int r = 0; r < 4; r++) {
                const int row = (tid >> 4) + 16 * r;
                const float4 v = *reinterpret_cast<const float4*>(
                    adj + ((size_t)(mBase + row) * (2 * L_DIM) + (size_t)k0 * 2 + s * 4));
                rv[r * 4 + 0] = v.x; rv[r * 4 + 1] = v.y;
                rv[r * 4 + 2] = v.z; rv[r * 4 + 3] = v.w;
            }
        } else {
            const int m   = tid & 63;
            const int oct = tid >> 6;          // 8 k's per thread
            #pragma unroll
            for (int j = 0; j < 8; j++) {
                const float2 v = *reinterpret_cast<const float2*>(
                    adj + ((size_t)(k0 + oct * 8 + j) * (2 * L_DIM) + (size_t)(mBase + m) * 2));
                rv[2 * j]     = v.x;
                rv[2 * j + 1] = v.y;
            }
        }
    };

    // ---- split rv, store A tile to smem buffer ----
    auto storeA = [&](int buf) {
        char* ahi = smem + OFF_AHI(buf);
        char* alo = smem + OFF_ALO(buf);
        if constexpr (!TRANS) {
            const int s = tid & 15;
            #pragma unroll
            for (int r = 0; r < 4; r++) {
                const int row = (tid >> 4) + 16 * r;
                __half ph, pl, qh, ql;
                f16_split(rv[r * 4 + 0] + rv[r * 4 + 1], ph, pl);
                f16_split(rv[r * 4 + 2] + rv[r * 4 + 3], qh, ql);
                const int o = (row * ASTRIDE + 2 * s) * 2;
                *reinterpret_cast<__half2*>(ahi + o) = __halves2half2(ph, qh);
                *reinterpret_cast<__half2*>(alo + o) = __halves2half2(pl, ql);
            }
        } else {
            const int m   = tid & 63;
            const int oct = tid >> 6;
            __half hh[8], ll[8];
            #pragma unroll
            for (int j = 0; j < 8; j++)
                f16_split(rv[2 * j] + rv[2 * j + 1], hh[j], ll[j]);
            const int o = (m * ASTRIDE + oct * 8) * 2;
            *reinterpret_cast<uint4*>(ahi + o) = *reinterpret_cast<const uint4*>(hh);
            *reinterpret_cast<uint4*>(alo + o) = *reinterpret_cast<const uint4*>(ll);
        }
    };

    // ---- B tiles via cp.async (pre-split halves in global) ----
    auto loadB = [&](int it, int buf) {
        const int k0 = kBase + it * BK;
        const uint32_t bhi = sbase + OFF_BHI(buf);
        const uint32_t blo = sbase + OFF_BLO(buf);
        #pragma unroll
        for (int r = 0; r < 5; r++) {
            const int idx = tid + 256 * r;          // 0..1279
            const int half_sel = idx >= 640;
            const int i2 = half_sel ? idx - 640 : idx;
            const int n = i2 >> 2;
            const int s = i2 & 3;
            const __half* src = (half_sel ? g_hT_lo : g_hT_hi)
                                + (size_t)n * L_DIM + k0 + s * 8;
            const uint32_t dst = (half_sel ? blo : bhi) + (n * BSTRIDE + s * 8) * 2;
            CPASYNC16(dst, src);
        }
    };

    auto compute = [&](int buf) {
        const uint32_t aHi = sbase + OFF_AHI(buf);
        const uint32_t aLo = sbase + OFF_ALO(buf);
        const uint32_t bHi = sbase + OFF_BHI(buf);
        const uint32_t bLo = sbase + OFF_BLO(buf);
        #pragma unroll
        for (int ks = 0; ks < 2; ks++) {
            const int kb = ks * 16;

            uint32_t ah[2][4], al[2][4];
            #pragma unroll
            for (int am = 0; am < 2; am++) {
                const uint32_t off =
                    ((wm * 32 + am * 16 + a_row) * ASTRIDE + kb + a_col) * 2;
                LDSM_X4(ah[am][0], ah[am][1], ah[am][2], ah[am][3], aHi + off);
                LDSM_X4(al[am][0], al[am][1], al[am][2], al[am][3], aLo + off);
            }

            uint32_t bh[5][2], bl[5][2];
            #pragma unroll
            for (int an = 0; an < 5; an++) {
                const uint32_t off =
                    ((wn * 40 + an * 8 + b_row) * BSTRIDE + kb + b_col) * 2;
                LDSM_X2(bh[an][0], bh[an][1], bHi + off);
                LDSM_X2(bl[an][0], bl[an][1], bLo + off);
            }

            #pragma unroll
            for (int am = 0; am < 2; am++)
                #pragma unroll
                for (int an = 0; an < 5; an++) {
                    float* c = acc[am][an];
                    MMA16816(c[0], c[1], c[2], c[3],
                             ah[am][0], ah[am][1], ah[am][2], ah[am][3],
                             bh[an][0], bh[an][1]);
                    MMA16816(c[0], c[1], c[2], c[3],
                             ah[am][0], ah[am][1], ah[am][2], ah[am][3],
                             bl[an][0], bl[an][1]);
                    MMA16816(c[0], c[1], c[2], c[3],
                             al[am][0], al[am][1], al[am][2], al[am][3],
                             bh[an][0], bh[an][1]);
                }
        }
    };

    // ---- prologue ----
    loadA(0);
    loadB(0, 0);
    CPCOMMIT();
    storeA(0);
    CPWAIT0();
    __syncthreads();

    // ---- pipelined mainloop ----
    for (int it = 0; it < NCHUNK; it++) {
        const int cur = it & 1;
        const int nxt = cur ^ 1;
        const bool more = (it + 1 < NCHUNK);
        if (more) {
            loadA(it + 1);        // LDG in flight over compute
            loadB(it + 1, nxt);   // cp.async in flight over compute
            CPCOMMIT();
        }
        compute(cur);
        if (more) {
            storeA(nxt);
            CPWAIT0();
        }
        __syncthreads();
    }

    // ---- epilogue ----
    float* sp = g_scratch + (size_t)blockIdx.y * ((size_t)L_DIM * DP);
    #pragma unroll
    for (int am = 0; am < 2; am++) {
        const int row = mBase + wm * 32 + am * 16 + qid;
        #pragma unroll
        for (int an = 0; an < 5; an++) {
            const int col = wn * 40 + an * 8 + qk * 2;
            *reinterpret_cast<float2*>(sp + (size_t)row * DP + col) =
                make_float2(acc[am][an][0], acc[am][an][1]);
            *reinterpret_cast<float2*>(sp + (size_t)(row + 8) * DP + col) =
                make_float2(acc[am][an][2], acc[am][an][3]);
        }
    }
}

__global__ void reduce_kernel(float* __restrict__ out)
{
    const int idx = blockIdx.x * 256 + threadIdx.x;
    if (idx >= L_DIM * D_DIM) return;
    const int row = idx / D_DIM;
    const int d   = idx - row * D_DIM;
    const size_t base = (size_t)row * DP + d;
    float s = 0.0f;
    #pragma unroll
    for (int sk = 0; sk < SPLITK; sk++)
        s += g_scratch[(size_t)sk * ((size_t)L_DIM * DP) + base];
    out[idx] = s;
}

extern "C" void kernel_launch(void* const* d_in, const int* in_sizes, int n_in,
                              void* d_out, int out_size)
{
    const float* adj = (const float*)d_in[0];   // [L, L, 2] fp32
    const float* h   = (const float*)d_in[1];   // [L, D]    fp32
    float* out = (float*)d_out;                 // [2, L, D] : h_in then h_out

    static bool attr_set = false;
    if (!attr_set) {
        cudaFuncSetAttribute(gemm_mma_kernel<false>,
                             cudaFuncAttributeMaxDynamicSharedMemorySize, SMEM_TOTAL);
        cudaFuncSetAttribute(gemm_mma_kernel<true>,
                             cudaFuncAttributeMaxDynamicSharedMemorySize, SMEM_TOTAL);
        attr_set = true;
    }

    prep_h_kernel<<<(DP * L_DIM) / 256, 256>>>(h);

    const dim3 grid(L_DIM / BM, SPLITK);
    const int  red_blocks = (L_DIM * D_DIM + 255) / 256;

    // h_out = A @ h  -> second half of output
    gemm_mma_kernel<false><<<grid, 256, SMEM_TOTAL>>>(adj);
    reduce_kernel<<<red_blocks, 256>>>(out + (size_t)L_DIM * D_DIM);

    // h_in = A^T @ h -> first half of output
    gemm_mma_kernel<true><<<grid, 256, SMEM_TOTAL>>>(adj);
    reduce_kernel<<<red_blocks, 256>>>(out);
}

// round 8
// speedup vs baseline: 3.0126x; 1.0432x over previous
#include <cuda_runtime.h>
#include <cuda_fp16.h>
#include <cstdint>
#include <cstddef>

#define L_DIM 4096
#define D_DIM 150
#define DP    160            // padded N
#define BM    64
#define BK    32             // 2 k16 steps per chunk
#define SPLITK 4
#define KCHUNK (L_DIM / SPLITK)   // 1024
#define NCHUNK (KCHUNK / BK)      // 32
#define ASTRIDE 40           // halves per A smem row (80B: LDSM conflict-free)
#define BSTRIDE 40
#define OUT_ELEMS (L_DIM * D_DIM)   // 614400

#define ATILE (BM * ASTRIDE * 2)   // 5120 B
#define BTILE (DP * BSTRIDE * 2)   // 12800 B
#define OFF_AHI(b) ((b) * ATILE)
#define OFF_ALO(b) (2 * ATILE + (b) * ATILE)
#define OFF_BHI(b) (4 * ATILE + (b) * BTILE)
#define OFF_BLO(b) (4 * ATILE + 2 * BTILE + (b) * BTILE)
#define SMEM_TOTAL (4 * ATILE + 4 * BTILE)   // 71680 B

__device__ float  g_s0[(size_t)SPLITK * L_DIM * DP];   // pass0 partials (10.5 MB)
__device__ float  g_s1[(size_t)SPLITK * L_DIM * DP];   // pass1 partials
__device__ __half g_hT_hi[(size_t)DP * L_DIM];         // [n][k] K-major
__device__ __half g_hT_lo[(size_t)DP * L_DIM];

#define MMA16816(c0,c1,c2,c3, a0,a1,a2,a3, b0,b1)                            \
    asm volatile("mma.sync.aligned.m16n8k16.row.col.f32.f16.f16.f32 "        \
                 "{%0,%1,%2,%3}, {%4,%5,%6,%7}, {%8,%9}, {%0,%1,%2,%3};"     \
                 : "+f"(c0), "+f"(c1), "+f"(c2), "+f"(c3)                    \
                 : "r"(a0), "r"(a1), "r"(a2), "r"(a3), "r"(b0), "r"(b1))

#define LDSM_X4(r0,r1,r2,r3, addr)                                           \
    asm volatile("ldmatrix.sync.aligned.m8n8.x4.shared.b16 {%0,%1,%2,%3}, [%4];" \
                 : "=r"(r0), "=r"(r1), "=r"(r2), "=r"(r3) : "r"(addr))

#define LDSM_X2(r0,r1, addr)                                                 \
    asm volatile("ldmatrix.sync.aligned.m8n8.x2.shared.b16 {%0,%1}, [%2];"   \
                 : "=r"(r0), "=r"(r1) : "r"(addr))

#define CPASYNC16(dst, src)                                                  \
    asm volatile("cp.async.cg.shared.global [%0], [%1], 16;" :: "r"(dst), "l"(src))
#define CPCOMMIT() asm volatile("cp.async.commit_group;")
#define CPWAIT0()  asm volatile("cp.async.wait_group 0;")

__device__ __forceinline__ void f16_split(float v, __half& hi, __half& lo) {
    hi = __float2half_rn(v);
    lo = __float2half_rn(v - __half2float(hi));
}

__global__ void prep_h_kernel(const float* __restrict__ h) {
    const int idx = blockIdx.x * 256 + threadIdx.x;   // DP*L
    const int n = idx >> 12;
    const int k = idx & (L_DIM - 1);
    float v = 0.0f;
    if (n < D_DIM) v = h[(size_t)k * D_DIM + n];
    __half hi, lo;
    f16_split(v, hi, lo);
    g_hT_hi[idx] = hi;
    g_hT_lo[idx] = lo;
}

// partial[split][m][d] = sum_{k in split} Aeff[m,k]*h[k,d]  via 3xFP16 mma.sync.
// FUSE_RED: additionally reduce rsrc (previous pass's 4 slabs) into rdst,
// executed in the shadow of the prologue's global-load latency.
template <bool TRANS, bool FUSE_RED>
__global__ __launch_bounds__(256)
void gemm_mma_kernel(const float* __restrict__ adj, float* __restrict__ sc,
                     const float* __restrict__ rsrc, float* __restrict__ rdst)
{
    extern __shared__ __align__(16) char smem[];
    uint32_t sbase;
    asm("{ .reg .u64 t; cvta.to.shared.u64 t, %1; cvt.u32.u64 %0, t; }"
        : "=r"(sbase) : "l"(smem));

    const int tid  = threadIdx.x;
    const int wid  = tid >> 5;
    const int lane = tid & 31;
    const int wm   = wid & 1;         // 2 x 32 rows
    const int wn   = wid >> 1;        // 4 x 40 cols
    const int qid  = lane >> 2;
    const int qk   = lane & 3;

    const int mBase = blockIdx.x * BM;
    const int kBase = blockIdx.y * KCHUNK;

    const int a_row = ((lane >> 3) & 1) * 8 + (lane & 7);
    const int a_col = (lane >> 4) * 8;
    const int b_row = lane & 7;
    const int b_col = ((lane >> 3) & 1) * 8;

    float acc[2][5][4];
    #pragma unroll
    for (int i = 0; i < 2; i++)
        #pragma unroll
        for (int j = 0; j < 5; j++)
            #pragma unroll
            for (int t = 0; t < 4; t++)
                acc[i][j][t] = 0.0f;

    float rv[16];

    auto loadA = [&](int it) {
        const int k0 = kBase + it * BK;
        if constexpr (!TRANS) {
            const int s = tid & 15;
            #pragma unroll
            for (int r = 0; r < 4; r++) {
                const int row = (tid >> 4) + 16 * r;
                const float4 v = *reinterpret_cast<const float4*>(
                    adj + ((size_t)(mBase + row) * (2 * L_DIM) + (size_t)k0 * 2 + s * 4));
                rv[r * 4 + 0] = v.x; rv[r * 4 + 1] = v.y;
                rv[r * 4 + 2] = v.z; rv[r * 4 + 3] = v.w;
            }
        } else {
            const int m   = tid & 63;
            const int oct = tid >> 6;
            #pragma unroll
            for (int j = 0; j < 8; j++) {
                const float2 v = *reinterpret_cast<const float2*>(
                    adj + ((size_t)(k0 + oct * 8 + j) * (2 * L_DIM) + (size_t)(mBase + m) * 2));
                rv[2 * j]     = v.x;
                rv[2 * j + 1] = v.y;
            }
        }
    };

    auto storeA = [&](int buf) {
        char* ahi = smem + OFF_AHI(buf);
        char* alo = smem + OFF_ALO(buf);
        if constexpr (!TRANS) {
            const int s = tid & 15;
            #pragma unroll
            for (int r = 0; r < 4; r++) {
                const int row = (tid >> 4) + 16 * r;
                __half ph, pl, qh, ql;
                f16_split(rv[r * 4 + 0] + rv[r * 4 + 1], ph, pl);
                f16_split(rv[r * 4 + 2] + rv[r * 4 + 3], qh, ql);
                const int o = (row * ASTRIDE + 2 * s) * 2;
                *reinterpret_cast<__half2*>(ahi + o) = __halves2half2(ph, qh);
                *reinterpret_cast<__half2*>(alo + o) = __halves2half2(pl, ql);
            }
        } else {
            const int m   = tid & 63;
            const int oct = tid >> 6;
            __half hh[8], ll[8];
            #pragma unroll
            for (int j = 0; j < 8; j++)
                f16_split(rv[2 * j] + rv[2 * j + 1], hh[j], ll[j]);
            const int o = (m * ASTRIDE + oct * 8) * 2;
            *reinterpret_cast<uint4*>(ahi + o) = *reinterpret_cast<const uint4*>(hh);
            *reinterpret_cast<uint4*>(alo + o) = *reinterpret_cast<const uint4*>(ll);
        }
    };

    auto loadB = [&](int it, int buf) {
        const int k0 = kBase + it * BK;
        const uint32_t bhi = sbase + OFF_BHI(buf);
        const uint32_t blo = sbase + OFF_BLO(buf);
        #pragma unroll
        for (int r = 0; r < 5; r++) {
            const int idx = tid + 256 * r;
            const int half_sel = idx >= 640;
            const int i2 = half_sel ? idx - 640 : idx;
            const int n = i2 >> 2;
            const int s = i2 & 3;
            const __half* src = (half_sel ? g_hT_lo : g_hT_hi)
                                + (size_t)n * L_DIM + k0 + s * 8;
            const uint32_t dst = (half_sel ? blo : bhi) + (n * BSTRIDE + s * 8) * 2;
            CPASYNC16(dst, src);
        }
    };

    auto compute = [&](int buf) {
        const uint32_t aHi = sbase + OFF_AHI(buf);
        const uint32_t aLo = sbase + OFF_ALO(buf);
        const uint32_t bHi = sbase + OFF_BHI(buf);
        const uint32_t bLo = sbase + OFF_BLO(buf);
        #pragma unroll
        for (int ks = 0; ks < 2; ks++) {
            const int kb = ks * 16;

            uint32_t ah[2][4], al[2][4];
            #pragma unroll
            for (int am = 0; am < 2; am++) {
                const uint32_t off =
                    ((wm * 32 + am * 16 + a_row) * ASTRIDE + kb + a_col) * 2;
                LDSM_X4(ah[am][0], ah[am][1], ah[am][2], ah[am][3], aHi + off);
                LDSM_X4(al[am][0], al[am][1], al[am][2], al[am][3], aLo + off);
            }

            uint32_t bh[5][2], bl[5][2];
            #pragma unroll
            for (int an = 0; an < 5; an++) {
                const uint32_t off =
                    ((wn * 40 + an * 8 + b_row) * BSTRIDE + kb + b_col) * 2;
                LDSM_X2(bh[an][0], bh[an][1], bHi + off);
                LDSM_X2(bl[an][0], bl[an][1], bLo + off);
            }

            #pragma unroll
            for (int am = 0; am < 2; am++)
                #pragma unroll
                for (int an = 0; an < 5; an++) {
                    float* c = acc[am][an];
                    MMA16816(c[0], c[1], c[2], c[3],
                             ah[am][0], ah[am][1], ah[am][2], ah[am][3],
                             bh[an][0], bh[an][1]);
                    MMA16816(c[0], c[1], c[2], c[3],
                             ah[am][0], ah[am][1], ah[am][2], ah[am][3],
                             bl[an][0], bl[an][1]);
                    MMA16816(c[0], c[1], c[2], c[3],
                             al[am][0], al[am][1], al[am][2], al[am][3],
                             bh[an][0], bh[an][1]);
                }
        }
    };

    // ---- prologue (loads in flight) ----
    loadA(0);
    loadB(0, 0);
    CPCOMMIT();

    // ---- fused reduce of previous pass, hidden under prologue load latency ----
    if constexpr (FUSE_RED) {
        const int g = (blockIdx.y * gridDim.x + blockIdx.x) * 256 + tid;  // 0..65535
        #pragma unroll
        for (int r = 0; r < 10; r++) {
            const int idx = g + r * 65536;
            if (idx < OUT_ELEMS) {
                const int row = idx / D_DIM;
                const int d   = idx - row * D_DIM;
                const size_t base = (size_t)row * DP + d;
                float s = rsrc[base]
                        + rsrc[(size_t)1 * L_DIM * DP + base]
                        + rsrc[(size_t)2 * L_DIM * DP + base]
                        + rsrc[(size_t)3 * L_DIM * DP + base];
                rdst[idx] = s;
            }
        }
    }

    storeA(0);
    CPWAIT0();
    __syncthreads();

    // ---- pipelined mainloop ----
    for (int it = 0; it < NCHUNK; it++) {
        const int cur = it & 1;
        const int nxt = cur ^ 1;
        const bool more = (it + 1 < NCHUNK);
        if (more) {
            loadA(it + 1);
            loadB(it + 1, nxt);
            CPCOMMIT();
        }
        compute(cur);
        if (more) {
            storeA(nxt);
            CPWAIT0();
        }
        __syncthreads();
    }

    // ---- epilogue ----
    float* sp = sc + (size_t)blockIdx.y * ((size_t)L_DIM * DP);
    #pragma unroll
    for (int am = 0; am < 2; am++) {
        const int row = mBase + wm * 32 + am * 16 + qid;
        #pragma unroll
        for (int an = 0; an < 5; an++) {
            const int col = wn * 40 + an * 8 + qk * 2;
            *reinterpret_cast<float2*>(sp + (size_t)row * DP + col) =
                make_float2(acc[am][an][0], acc[am][an][1]);
            *reinterpret_cast<float2*>(sp + (size_t)(row + 8) * DP + col) =
                make_float2(acc[am][an][2], acc[am][an][3]);
        }
    }
}

// Tail reduction for the last pass
__global__ void reduce_kernel(const float* __restrict__ src, float* __restrict__ out)
{
    const int idx = blockIdx.x * 256 + threadIdx.x;
    if (idx >= OUT_ELEMS) return;
    const int row = idx / D_DIM;
    const int d   = idx - row * D_DIM;
    const size_t base = (size_t)row * DP + d;
    out[idx] = src[base]
             + src[(size_t)1 * L_DIM * DP + base]
             + src[(size_t)2 * L_DIM * DP + base]
             + src[(size_t)3 * L_DIM * DP + base];
}

extern "C" void kernel_launch(void* const* d_in, const int* in_sizes, int n_in,
                              void* d_out, int out_size)
{
    const float* adj = (const float*)d_in[0];   // [L, L, 2] fp32
    const float* h   = (const float*)d_in[1];   // [L, D]    fp32
    float* out = (float*)d_out;                 // [2, L, D] : h_in then h_out

    static bool attr_set = false;
    if (!attr_set) {
        cudaFuncSetAttribute(gemm_mma_kernel<false, false>,
                             cudaFuncAttributeMaxDynamicSharedMemorySize, SMEM_TOTAL);
        cudaFuncSetAttribute(gemm_mma_kernel<true, true>,
                             cudaFuncAttributeMaxDynamicSharedMemorySize, SMEM_TOTAL);
        attr_set = true;
    }

    float* s0; cudaGetSymbolAddress((void**)&s0, g_s0);
    float* s1; cudaGetSymbolAddress((void**)&s1, g_s1);

    prep_h_kernel<<<(DP * L_DIM) / 256, 256>>>(h);

    const dim3 grid(L_DIM / BM, SPLITK);
    const int  red_blocks = (OUT_ELEMS + 255) / 256;

    // pass0: h_out = A @ h -> partials in s0
    gemm_mma_kernel<false, false><<<grid, 256, SMEM_TOTAL>>>(adj, s0, nullptr, nullptr);
    // pass1: h_in = A^T @ h -> partials in s1; also reduces s0 -> out[second half]
    gemm_mma_kernel<true, true><<<grid, 256, SMEM_TOTAL>>>(
        adj, s1, s0, out + (size_t)OUT_ELEMS);
    // tail: reduce s1 -> out[first half]
    reduce_kernel<<<red_blocks, 256>>>(s1, out);
}

// round 9
// speedup vs baseline: 3.0951x; 1.0274x over previous
#include <cuda_runtime.h>
#include <cuda_fp16.h>
#include <cstdint>
#include <cstddef>

#define L_DIM 4096
#define D_DIM 150
#define DP    160            // padded N
#define BM    64
#define BK    32             // 2 k16 steps per chunk
#define SPLITK 4
#define KCHUNK (L_DIM / SPLITK)   // 1024
#define NCHUNK (KCHUNK / BK)      // 32
#define ASTRIDE 40           // halves per A smem row (80B: LDSM conflict-free)
#define BSTRIDE 40
#define OUT_ELEMS (L_DIM * D_DIM)   // 614400

#define ATILE (BM * ASTRIDE * 2)   // 5120 B
#define BTILE (DP * BSTRIDE * 2)   // 12800 B
#define OFF_AHI(b) ((b) * ATILE)
#define OFF_ALO(b) (2 * ATILE + (b) * ATILE)
#define OFF_BHI(b) (4 * ATILE + (b) * BTILE)
#define OFF_BLO(b) (4 * ATILE + 2 * BTILE + (b) * BTILE)
#define SMEM_TOTAL (4 * ATILE + 4 * BTILE)   // 71680 B

__device__ float  g_s0[(size_t)SPLITK * L_DIM * DP];   // h_out partials
__device__ float  g_s1[(size_t)SPLITK * L_DIM * DP];   // h_in partials
__device__ __half g_hT_hi[(size_t)DP * L_DIM];         // [n][k] K-major
__device__ __half g_hT_lo[(size_t)DP * L_DIM];

#define MMA16816(c0,c1,c2,c3, a0,a1,a2,a3, b0,b1)                            \
    asm volatile("mma.sync.aligned.m16n8k16.row.col.f32.f16.f16.f32 "        \
                 "{%0,%1,%2,%3}, {%4,%5,%6,%7}, {%8,%9}, {%0,%1,%2,%3};"     \
                 : "+f"(c0), "+f"(c1), "+f"(c2), "+f"(c3)                    \
                 : "r"(a0), "r"(a1), "r"(a2), "r"(a3), "r"(b0), "r"(b1))

#define LDSM_X4(r0,r1,r2,r3, addr)                                           \
    asm volatile("ldmatrix.sync.aligned.m8n8.x4.shared.b16 {%0,%1,%2,%3}, [%4];" \
                 : "=r"(r0), "=r"(r1), "=r"(r2), "=r"(r3) : "r"(addr))

#define LDSM_X2(r0,r1, addr)                                                 \
    asm volatile("ldmatrix.sync.aligned.m8n8.x2.shared.b16 {%0,%1}, [%2];"   \
                 : "=r"(r0), "=r"(r1) : "r"(addr))

#define CPASYNC16(dst, src)                                                  \
    asm volatile("cp.async.cg.shared.global [%0], [%1], 16;" :: "r"(dst), "l"(src))
#define CPCOMMIT() asm volatile("cp.async.commit_group;")
#define CPWAIT0()  asm volatile("cp.async.wait_group 0;")

__device__ __forceinline__ void f16_split(float v, __half& hi, __half& lo) {
    hi = __float2half_rn(v);
    lo = __float2half_rn(v - __half2float(hi));
}

__global__ void prep_h_kernel(const float* __restrict__ h) {
    const int idx = blockIdx.x * 256 + threadIdx.x;   // DP*L
    const int n = idx >> 12;
    const int k = idx & (L_DIM - 1);
    float v = 0.0f;
    if (n < D_DIM) v = h[(size_t)k * D_DIM + n];
    __half hi, lo;
    f16_split(v, hi, lo);
    g_hT_hi[idx] = hi;
    g_hT_lo[idx] = lo;
}

// partial[split][m][d] = sum_{k in split} Aeff[m,k]*h[k,d]  via 3xFP16 mma.sync
template <bool TRANS>
__device__ __forceinline__
void gemm_body(const float* __restrict__ adj, float* __restrict__ sc, char* smem)
{
    uint32_t sbase;
    asm("{ .reg .u64 t; cvta.to.shared.u64 t, %1; cvt.u32.u64 %0, t; }"
        : "=r"(sbase) : "l"(smem));

    const int tid  = threadIdx.x;
    const int wid  = tid >> 5;
    const int lane = tid & 31;
    const int wm   = wid & 1;         // 2 x 32 rows
    const int wn   = wid >> 1;        // 4 x 40 cols
    const int qid  = lane >> 2;
    const int qk   = lane & 3;

    const int mBase = blockIdx.x * BM;
    const int kBase = blockIdx.y * KCHUNK;

    const int a_row = ((lane >> 3) & 1) * 8 + (lane & 7);
    const int a_col = (lane >> 4) * 8;
    const int b_row = lane & 7;
    const int b_col = ((lane >> 3) & 1) * 8;

    float acc[2][5][4];
    #pragma unroll
    for (int i = 0; i < 2; i++)
        #pragma unroll
        for (int j = 0; j < 5; j++)
            #pragma unroll
            for (int t = 0; t < 4; t++)
                acc[i][j][t] = 0.0f;

    float rv[16];

    auto loadA = [&](int it) {
        const int k0 = kBase + it * BK;
        if constexpr (!TRANS) {
            const int s = tid & 15;
            #pragma unroll
            for (int r = 0; r < 4; r++) {
                const int row = (tid >> 4) + 16 * r;
                const float4 v = *reinterpret_cast<const float4*>(
                    adj + ((size_t)(mBase + row) * (2 * L_DIM) + (size_t)k0 * 2 + s * 4));
                rv[r * 4 + 0] = v.x; rv[r * 4 + 1] = v.y;
                rv[r * 4 + 2] = v.z; rv[r * 4 + 3] = v.w;
            }
        } else {
            const int m   = tid & 63;
            const int oct = tid >> 6;
            #pragma unroll
            for (int j = 0; j < 8; j++) {
                const float2 v = *reinterpret_cast<const float2*>(
                    adj + ((size_t)(k0 + oct * 8 + j) * (2 * L_DIM) + (size_t)(mBase + m) * 2));
                rv[2 * j]     = v.x;
                rv[2 * j + 1] = v.y;
            }
        }
    };

    auto storeA = [&](int buf) {
        char* ahi = smem + OFF_AHI(buf);
        char* alo = smem + OFF_ALO(buf);
        if constexpr (!TRANS) {
            const int s = tid & 15;
            #pragma unroll
            for (int r = 0; r < 4; r++) {
                const int row = (tid >> 4) + 16 * r;
                __half ph, pl, qh, ql;
                f16_split(rv[r * 4 + 0] + rv[r * 4 + 1], ph, pl);
                f16_split(rv[r * 4 + 2] + rv[r * 4 + 3], qh, ql);
                const int o = (row * ASTRIDE + 2 * s) * 2;
                *reinterpret_cast<__half2*>(ahi + o) = __halves2half2(ph, qh);
                *reinterpret_cast<__half2*>(alo + o) = __halves2half2(pl, ql);
            }
        } else {
            const int m   = tid & 63;
            const int oct = tid >> 6;
            __half hh[8], ll[8];
            #pragma unroll
            for (int j = 0; j < 8; j++)
                f16_split(rv[2 * j] + rv[2 * j + 1], hh[j], ll[j]);
            const int o = (m * ASTRIDE + oct * 8) * 2;
            *reinterpret_cast<uint4*>(ahi + o) = *reinterpret_cast<const uint4*>(hh);
            *reinterpret_cast<uint4*>(alo + o) = *reinterpret_cast<const uint4*>(ll);
        }
    };

    auto loadB = [&](int it, int buf) {
        const int k0 = kBase + it * BK;
        const uint32_t bhi = sbase + OFF_BHI(buf);
        const uint32_t blo = sbase + OFF_BLO(buf);
        #pragma unroll
        for (int r = 0; r < 5; r++) {
            const int idx = tid + 256 * r;
            const int half_sel = idx >= 640;
            const int i2 = half_sel ? idx - 640 : idx;
            const int n = i2 >> 2;
            const int s = i2 & 3;
            const __half* src = (half_sel ? g_hT_lo : g_hT_hi)
                                + (size_t)n * L_DIM + k0 + s * 8;
            const uint32_t dst = (half_sel ? blo : bhi) + (n * BSTRIDE + s * 8) * 2;
            CPASYNC16(dst, src);
        }
    };

    auto compute = [&](int buf) {
        const uint32_t aHi = sbase + OFF_AHI(buf);
        const uint32_t aLo = sbase + OFF_ALO(buf);
        const uint32_t bHi = sbase + OFF_BHI(buf);
        const uint32_t bLo = sbase + OFF_BLO(buf);
        #pragma unroll
        for (int ks = 0; ks < 2; ks++) {
            const int kb = ks * 16;

            uint32_t ah[2][4], al[2][4];
            #pragma unroll
            for (int am = 0; am < 2; am++) {
                const uint32_t off =
                    ((wm * 32 + am * 16 + a_row) * ASTRIDE + kb + a_col) * 2;
                LDSM_X4(ah[am][0], ah[am][1], ah[am][2], ah[am][3], aHi + off);
                LDSM_X4(al[am][0], al[am][1], al[am][2], al[am][3], aLo + off);
            }

            uint32_t bh[5][2], bl[5][2];
            #pragma unroll
            for (int an = 0; an < 5; an++) {
                const uint32_t off =
                    ((wn * 40 + an * 8 + b_row) * BSTRIDE + kb + b_col) * 2;
                LDSM_X2(bh[an][0], bh[an][1], bHi + off);
                LDSM_X2(bl[an][0], bl[an][1], bLo + off);
            }

            #pragma unroll
            for (int am = 0; am < 2; am++)
                #pragma unroll
                for (int an = 0; an < 5; an++) {
                    float* c = acc[am][an];
                    MMA16816(c[0], c[1], c[2], c[3],
                             ah[am][0], ah[am][1], ah[am][2], ah[am][3],
                             bh[an][0], bh[an][1]);
                    MMA16816(c[0], c[1], c[2], c[3],
                             ah[am][0], ah[am][1], ah[am][2], ah[am][3],
                             bl[an][0], bl[an][1]);
                    MMA16816(c[0], c[1], c[2], c[3],
                             al[am][0], al[am][1], al[am][2], al[am][3],
                             bh[an][0], bh[an][1]);
                }
        }
    };

    // ---- prologue ----
    loadA(0);
    loadB(0, 0);
    CPCOMMIT();
    storeA(0);
    CPWAIT0();
    __syncthreads();

    // ---- pipelined mainloop ----
    for (int it = 0; it < NCHUNK; it++) {
        const int cur = it & 1;
        const int nxt = cur ^ 1;
        const bool more = (it + 1 < NCHUNK);
        if (more) {
            loadA(it + 1);
            loadB(it + 1, nxt);
            CPCOMMIT();
        }
        compute(cur);
        if (more) {
            storeA(nxt);
            CPWAIT0();
        }
        __syncthreads();
    }

    // ---- epilogue ----
    float* sp = sc + (size_t)blockIdx.y * ((size_t)L_DIM * DP);
    #pragma unroll
    for (int am = 0; am < 2; am++) {
        const int row = mBase + wm * 32 + am * 16 + qid;
        #pragma unroll
        for (int an = 0; an < 5; an++) {
            const int col = wn * 40 + an * 8 + qk * 2;
            *reinterpret_cast<float2*>(sp + (size_t)row * DP + col) =
                make_float2(acc[am][an][0], acc[am][an][1]);
            *reinterpret_cast<float2*>(sp + (size_t)(row + 8) * DP + col) =
                make_float2(acc[am][an][2], acc[am][an][3]);
        }
    }
}

// Both orientations co-scheduled in one launch: blockIdx.z selects the body.
__global__ __launch_bounds__(256)
void gemm_fused_kernel(const float* __restrict__ adj,
                       float* __restrict__ s0, float* __restrict__ s1)
{
    extern __shared__ __align__(16) char smem[];
    if (blockIdx.z == 0)
        gemm_body<false>(adj, s0, smem);   // h_out = A @ h
    else
        gemm_body<true>(adj, s1, smem);    // h_in  = A^T @ h
}

// Single tail reduction for both halves:
// out[0..OUT)   = h_in  from s1;  out[OUT..2*OUT) = h_out from s0
__global__ void reduce_both_kernel(const float* __restrict__ s0,
                                   const float* __restrict__ s1,
                                   float* __restrict__ out)
{
    const int idx = blockIdx.x * 256 + threadIdx.x;
    if (idx >= 2 * OUT_ELEMS) return;
    const int sel   = idx >= OUT_ELEMS;
    const int local = sel ? idx - OUT_ELEMS : idx;
    const float* src = sel ? s0 : s1;
    const int row = local / D_DIM;
    const int d   = local - row * D_DIM;
    const size_t base = (size_t)row * DP + d;
    out[idx] = src[base]
             + src[(size_t)1 * L_DIM * DP + base]
             + src[(size_t)2 * L_DIM * DP + base]
             + src[(size_t)3 * L_DIM * DP + base];
}

extern "C" void kernel_launch(void* const* d_in, const int* in_sizes, int n_in,
                              void* d_out, int out_size)
{
    const float* adj = (const float*)d_in[0];   // [L, L, 2] fp32
    const float* h   = (const float*)d_in[1];   // [L, D]    fp32
    float* out = (float*)d_out;                 // [2, L, D] : h_in then h_out

    static bool attr_set = false;
    if (!attr_set) {
        cudaFuncSetAttribute(gemm_fused_kernel,
                             cudaFuncAttributeMaxDynamicSharedMemorySize, SMEM_TOTAL);
        attr_set = true;
    }

    float* s0; cudaGetSymbolAddress((void**)&s0, g_s0);
    float* s1; cudaGetSymbolAddress((void**)&s1, g_s1);

    prep_h_kernel<<<(DP * L_DIM) / 256, 256>>>(h);

    const dim3 grid(L_DIM / BM, SPLITK, 2);            // 512 CTAs, both passes
    gemm_fused_kernel<<<grid, 256, SMEM_TOTAL>>>(adj, s0, s1);

    const int red_blocks = (2 * OUT_ELEMS + 255) / 256;
    reduce_both_kernel<<<red_blocks, 256>>>(s0, s1, out);
}